// round 16
// baseline (speedup 1.0000x reference)
#include <cuda_runtime.h>
#include <cuda_fp16.h>
#include <cstdint>

// ---------------- problem constants ----------------
#define NTOK  197
#define BTOT  128          // B*T
#define OC3   2304         // 3*C
#define NCOLS 25216        // BTOT*NTOK
#define OUTBT 453888       // OC3*NTOK

// ---------------- device scratch (static globals: allowed) ----------------
__device__ float  g_s[BTOT * OC3];              // routing scales, 1.18 MB
__device__ float  g_rp[6][BTOT * OC3];          // split-K partials, 7.1 MB
__device__ __half g_wth[OC3 * 768];             // fp16(W), 3.5 MB
__device__ __half g_xsh[3][NCOLS * 768];        // fp16(x*s) per group, 116 MB
__device__ __half g_awh[OC3 * 2304];            // fp16(a_weight), 10.6 MB
__device__ __half g_clsh[BTOT * 2304];          // fp16 im2col cls, 0.59 MB

// ---------------- helpers ----------------
__device__ __forceinline__ uint32_t smem_u32(const void* p) {
    uint32_t a;
    asm("{ .reg .u64 t; cvta.to.shared.u64 t, %1; cvt.u32.u64 %0, t; }" : "=r"(a) : "l"(p));
    return a;
}
__device__ __forceinline__ void cp_async16(uint32_t dst, const void* src) {
    asm volatile("cp.async.cg.shared.global [%0], [%1], 16;" :: "r"(dst), "l"(src) : "memory");
}
#define CP_COMMIT() asm volatile("cp.async.commit_group;" ::: "memory")
#define CP_WAIT1()  asm volatile("cp.async.wait_group 1;" ::: "memory")

#define LDSM_X4(r0, r1, r2, r3, addr) \
    asm volatile("ldmatrix.sync.aligned.m8n8.x4.shared.b16 {%0,%1,%2,%3}, [%4];" \
        : "=r"(r0), "=r"(r1), "=r"(r2), "=r"(r3) : "r"(addr))

#define SWZ(off) ((off) ^ (((off) >> 3) & 0x70))

#define MMA16816(acc, a, b0, b1) \
    asm volatile( \
        "mma.sync.aligned.m16n8k16.row.col.f32.f16.f16.f32 " \
        "{%0,%1,%2,%3},{%4,%5,%6,%7},{%8,%9},{%0,%1,%2,%3};\n" \
        : "+f"((acc)[0]), "+f"((acc)[1]), "+f"((acc)[2]), "+f"((acc)[3]) \
        : "r"((a)[0]), "r"((a)[1]), "r"((a)[2]), "r"((a)[3]), "r"(b0), "r"(b1))

// ---------------------------------------------------------------------------
// prep_all: fused independent converters, dispatched by blockIdx range.
//   [0, 5184)        : a_weight fp32 -> fp16
//   [5184, 6912)     : W fp32 -> fp16
//   [6912, 7040)     : build_cls im2col fp16
// ---------------------------------------------------------------------------
__global__ __launch_bounds__(256) void prep_all(
    const float* __restrict__ aw, const float* __restrict__ w,
    const float* __restrict__ x)
{
    const int bid = blockIdx.x;
    if (bid < 5184) {
        int i = (bid * 256 + threadIdx.x) * 4;
        float4 v = *(const float4*)(aw + i);
        __half2 h0 = __floats2half2_rn(v.x, v.y);
        __half2 h1 = __floats2half2_rn(v.z, v.w);
        uint2 o = { *(uint32_t*)&h0, *(uint32_t*)&h1 };
        *(uint2*)(&g_awh[i]) = o;
    } else if (bid < 6912) {
        int i = ((bid - 5184) * 256 + threadIdx.x) * 4;
        float4 v = *(const float4*)(w + i);
        __half2 h0 = __floats2half2_rn(v.x, v.y);
        __half2 h1 = __floats2half2_rn(v.z, v.w);
        uint2 o = { *(uint32_t*)&h0, *(uint32_t*)&h1 };
        *(uint2*)(&g_wth[i]) = o;
    } else {
        const int bt = bid - 6912;
        const int b  = bt >> 3, t = bt & 7;
        __half* dst = g_clsh + (size_t)bt * 2304;
        for (int j = threadIdx.x; j < 2304; j += 256) {
            const int ic = j / 3, k = j - ic * 3;
            const int tq = t + k - 1;
            float v = 0.f;
            if (tq >= 0 && tq < 8)
                v = x[(size_t)((b * 8 + tq) * 197) * 768 + ic];
            dst[j] = __float2half_rn(v);
        }
    }
}

// ---------------------------------------------------------------------------
// routing_gemm (split-K x6): partial[oc, bt] = sum_{j in K-slice} awh*clsh
// grid = (18 m-tiles, 6 k-slices), block 128. 6 chunks each.
// ---------------------------------------------------------------------------
#define RSTAGES      3
#define RSTAGE_BYTES 32768
#define SMEM_RT      (RSTAGES * RSTAGE_BYTES)
#define RNCHUNK      6           // 2304/6/64

__global__ __launch_bounds__(128, 2)
void routing_gemm()
{
    extern __shared__ char smem[];
    const uint32_t sb = smem_u32(smem);

    const int mt   = blockIdx.x;          // 128-oc tile
    const int ky   = blockIdx.y;          // K slice
    const int tid  = threadIdx.x;
    const int lane = tid & 31, warp = tid >> 5;
    const int wm = warp & 1, wn = warp >> 1;
    const int lr = lane >> 2, lc = lane & 3;

    const int r0 = tid >> 3, q8 = (tid & 7) * 8;
    const uint32_t dst0 = SWZ((uint32_t)(r0 * 128 + q8 * 2));
    const __half* aptr = g_awh + (size_t)(mt * 128 + r0) * 2304 + ky * 384 + q8;
    const __half* bptr = g_clsh + (size_t)r0 * 2304 + ky * 384 + q8;

    const int alrow = lane & 15, aqhi = lane >> 4;
    const int brow = (lane & 7) | ((lane & 16) >> 1), bq = (lane >> 3) & 1;
    uint32_t aoff[4], boff[4];
    #pragma unroll
    for (int mi = 0; mi < 4; mi++)
        aoff[mi] = SWZ((uint32_t)((wm * 64 + mi * 16 + alrow) * 128 + aqhi * 16));
    #pragma unroll
    for (int nj = 0; nj < 4; nj++)
        boff[nj] = SWZ((uint32_t)((wn * 64 + nj * 16 + brow) * 128 + bq * 16));

    float acc[4][8][4];
    #pragma unroll
    for (int mi = 0; mi < 4; mi++)
        #pragma unroll
        for (int ni = 0; ni < 8; ni++)
            #pragma unroll
            for (int e = 0; e < 4; e++) acc[mi][ni][e] = 0.f;

    auto COPY = [&](int st, int c) {
        const uint32_t sA = sb + st * RSTAGE_BYTES;
        const uint32_t sB = sA + 16384;
        const __half* ap = aptr + c * 64;
        const __half* bp = bptr + c * 64;
        #pragma unroll
        for (int i = 0; i < 8; i++) {
            cp_async16(sA + dst0 + i * 2048, ap + (size_t)i * 36864);
            cp_async16(sB + dst0 + i * 2048, bp + (size_t)i * 36864);
        }
    };

    COPY(0, 0); CP_COMMIT();
    COPY(1, 1); CP_COMMIT();

    int st = 0, pf = 2;
    #pragma unroll 1
    for (int c = 0; c < RNCHUNK; c++) {
        CP_WAIT1();
        __syncthreads();
        if (c + 2 < RNCHUNK) COPY(pf, c + 2);
        CP_COMMIT();

        const uint32_t sA = sb + st * RSTAGE_BYTES;
        const uint32_t sB = sA + 16384;
        #pragma unroll
        for (int ks = 0; ks < 4; ks++) {
            const uint32_t kx = (uint32_t)(ks * 32);
            uint32_t a[4][4], b[4][4];
            #pragma unroll
            for (int mi = 0; mi < 4; mi++)
                LDSM_X4(a[mi][0], a[mi][1], a[mi][2], a[mi][3], sA + (aoff[mi] ^ kx));
            #pragma unroll
            for (int nj = 0; nj < 4; nj++)
                LDSM_X4(b[nj][0], b[nj][1], b[nj][2], b[nj][3], sB + (boff[nj] ^ kx));
            #pragma unroll
            for (int mi = 0; mi < 4; mi++)
                #pragma unroll
                for (int ni = 0; ni < 8; ni++)
                    MMA16816(acc[mi][ni], a[mi],
                             b[ni >> 1][(ni & 1) * 2], b[ni >> 1][(ni & 1) * 2 + 1]);
        }
        st = (st + 1 == 3) ? 0 : st + 1;
        pf = (pf + 1 == 3) ? 0 : pf + 1;
    }

    float* rp = g_rp[ky];
    #pragma unroll
    for (int mi = 0; mi < 4; mi++)
        #pragma unroll
        for (int ni = 0; ni < 8; ni++)
            #pragma unroll
            for (int e = 0; e < 4; e++) {
                const int h  = e >> 1;
                const int oc = mt * 128 + wm * 64 + mi * 16 + lr + h * 8;
                const int bt = wn * 64 + ni * 8 + lc * 2 + (e & 1);
                rp[bt * 2304 + oc] = acc[mi][ni][e];
            }
}

// ---------------------------------------------------------------------------
// combine_s: g_s = ab + 1 + sum of 6 partials (deterministic)
// ---------------------------------------------------------------------------
__global__ __launch_bounds__(256) void combine_s(const float* __restrict__ ab)
{
    int i4 = (blockIdx.x * 256 + threadIdx.x) * 4;   // < 294912
    int oc = i4 % 2304;
    float4 a  = *(const float4*)(ab + oc);
    float4 r0 = *(const float4*)(&g_rp[0][i4]);
    float4 r1 = *(const float4*)(&g_rp[1][i4]);
    float4 r2 = *(const float4*)(&g_rp[2][i4]);
    float4 r3 = *(const float4*)(&g_rp[3][i4]);
    float4 r4 = *(const float4*)(&g_rp[4][i4]);
    float4 r5 = *(const float4*)(&g_rp[5][i4]);
    float4 o;
    o.x = a.x + 1.0f + (((r0.x + r1.x) + (r2.x + r3.x)) + (r4.x + r5.x));
    o.y = a.y + 1.0f + (((r0.y + r1.y) + (r2.y + r3.y)) + (r4.y + r5.y));
    o.z = a.z + 1.0f + (((r0.z + r1.z) + (r2.z + r3.z)) + (r4.z + r5.z));
    o.w = a.w + 1.0f + (((r0.w + r1.w) + (r2.w + r3.w)) + (r4.w + r5.w));
    *(float4*)(&g_s[i4]) = o;
}

// ---------------------------------------------------------------------------
// xs_fused: g_xsh[g][col, k] = fp16(x[col,k] * s[bt(col), g, k])
// Thread owns (bt, g, k8); loads its 8 scale values ONCE, loops ~50 cols.
// grid = (4 colchunks, 3 g, 128 bt), block 96 (k8 slots). Coalesced 1KB/warp.
// ---------------------------------------------------------------------------
__global__ __launch_bounds__(96) void xs_fused(const float* __restrict__ x)
{
    const int k8 = threadIdx.x * 8;
    const int g  = blockIdx.y;
    const int bt = blockIdx.z;
    const int c0 = blockIdx.x * 50;
    const int c1 = (c0 + 50 < 197) ? (c0 + 50) : 197;

    float s0x, s0y, s0z, s0w, s1x, s1y, s1z, s1w;
    {
        const float* sp = g_s + bt * 2304 + g * 768 + k8;
        float4 s0 = *(const float4*)sp;
        float4 s1 = *(const float4*)(sp + 4);
        s0x = s0.x; s0y = s0.y; s0z = s0.z; s0w = s0.w;
        s1x = s1.x; s1y = s1.y; s1z = s1.z; s1w = s1.w;
    }

    const float* xp = x + ((size_t)bt * 197 + c0) * 768 + k8;
    __half*      op = g_xsh[g] + ((size_t)bt * 197 + c0) * 768 + k8;

    #pragma unroll 2
    for (int c = c0; c < c1; c++) {
        float4 x0 = *(const float4*)xp;
        float4 x1 = *(const float4*)(xp + 4);
        __half2 h0 = __floats2half2_rn(x0.x * s0x, x0.y * s0y);
        __half2 h1 = __floats2half2_rn(x0.z * s0z, x0.w * s0w);
        __half2 h2 = __floats2half2_rn(x1.x * s1x, x1.y * s1y);
        __half2 h3 = __floats2half2_rn(x1.z * s1z, x1.w * s1w);
        uint4 o = { *(uint32_t*)&h0, *(uint32_t*)&h1,
                    *(uint32_t*)&h2, *(uint32_t*)&h3 };
        *(uint4*)op = o;
        xp += 768; op += 768;
    }
}

// ---------------------------------------------------------------------------
// Main GEMM (mma.sync fp16 m16n8k16), PERSISTENT: grid=296 (2 CTA/SM).
// CTA tile 128x128, BK=64, 12 chunks, 3-stage cp.async ring continuous
// ACROSS tiles. 4 warps = 2x2, warp tile 64x64.
// ---------------------------------------------------------------------------
#define STAGES      3
#define STAGE_BYTES 32768            // A 16K + B 16K
#define SMEM_MAIN   (STAGES * STAGE_BYTES)
#define NCHUNK      12
#define NT_TILES    3546             // 18 * 197
#define NPERS       296

__global__ __launch_bounds__(128, 2)
void tal_main_kernel(const float* __restrict__ bias, float* __restrict__ out)
{
    extern __shared__ char smem[];
    const uint32_t sb = smem_u32(smem);

    const int tid  = threadIdx.x;
    const int lane = tid & 31, warp = tid >> 5;
    const int wm = warp & 1, wn = warp >> 1;      // 2x2 warp grid, 64x64 tiles
    const int lr = lane >> 2, lc = lane & 3;

    const int r0 = tid >> 3, q8 = (tid & 7) * 8;
    const uint32_t dst0 = SWZ((uint32_t)(r0 * 128 + q8 * 2));

    const int alrow = lane & 15, aqhi = lane >> 4;
    const int brow = (lane & 7) | ((lane & 16) >> 1), bq = (lane >> 3) & 1;
    uint32_t aoff[4], boff[4];
    #pragma unroll
    for (int mi = 0; mi < 4; mi++)
        aoff[mi] = SWZ((uint32_t)((wm * 64 + mi * 16 + alrow) * 128 + aqhi * 16));
    #pragma unroll
    for (int nj = 0; nj < 4; nj++)
        boff[nj] = SWZ((uint32_t)((wn * 64 + nj * 16 + brow) * 128 + bq * 16));

    auto mk_ptrs = [&](int t, const __half*& ap, const __half*& bp) {
        const int bx = t % 18;
        const int y  = t / 18;
        const int g  = bx / 6, mt = bx % 6;
        ap = g_wth + (size_t)(g * 768 + mt * 128 + r0) * 768 + q8;
        bp = g_xsh[g] + (size_t)(y * 128 + r0) * 768 + q8;
    };
    auto COPY = [&](int st, const __half* ap, const __half* bp, int c) {
        const uint32_t sA = sb + st * STAGE_BYTES;
        const uint32_t sB = sA + 16384;
        const __half* a8 = ap + c * 64;
        const __half* b8 = bp + c * 64;
        #pragma unroll
        for (int i = 0; i < 8; i++) {
            cp_async16(sA + dst0 + i * 2048, a8 + i * 12288);
            cp_async16(sB + dst0 + i * 2048, b8 + i * 12288);
        }
    };

    int t = blockIdx.x;
    const __half *ap, *bp;
    mk_ptrs(t, ap, bp);
    COPY(0, ap, bp, 0); CP_COMMIT();
    COPY(1, ap, bp, 1); CP_COMMIT();

    while (true) {
        const int  tn       = t + NPERS;
        const bool has_next = tn < NT_TILES;
        const __half *apN = ap, *bpN = bp;
        if (has_next) mk_ptrs(tn, apN, bpN);

        float acc[4][8][4];
        #pragma unroll
        for (int mi = 0; mi < 4; mi++)
            #pragma unroll
            for (int ni = 0; ni < 8; ni++)
                #pragma unroll
                for (int e = 0; e < 4; e++) acc[mi][ni][e] = 0.f;

        #pragma unroll 1
        for (int c = 0; c < NCHUNK; c++) {
            CP_WAIT1();
            __syncthreads();
            const int pst = (c + 2) % 3;
            if (c < NCHUNK - 2)      COPY(pst, ap, bp, c + 2);
            else if (has_next)       COPY(pst, apN, bpN, c + 2 - NCHUNK);
            CP_COMMIT();

            const uint32_t sA = sb + (c % 3) * STAGE_BYTES;
            const uint32_t sB = sA + 16384;
            #pragma unroll
            for (int ks = 0; ks < 4; ks++) {
                const uint32_t kx = (uint32_t)(ks * 32);
                uint32_t a[4][4], b[4][4];
                #pragma unroll
                for (int mi = 0; mi < 4; mi++)
                    LDSM_X4(a[mi][0], a[mi][1], a[mi][2], a[mi][3], sA + (aoff[mi] ^ kx));
                #pragma unroll
                for (int nj = 0; nj < 4; nj++)
                    LDSM_X4(b[nj][0], b[nj][1], b[nj][2], b[nj][3], sB + (boff[nj] ^ kx));
                #pragma unroll
                for (int mi = 0; mi < 4; mi++)
                    #pragma unroll
                    for (int ni = 0; ni < 8; ni++)
                        MMA16816(acc[mi][ni], a[mi],
                                 b[ni >> 1][(ni & 1) * 2], b[ni >> 1][(ni & 1) * 2 + 1]);
            }
        }

        // ---- epilogue for tile t (overlaps in-flight next-tile copies) ----
        {
            const int bx = t % 18, y = t / 18;
            const int g = bx / 6, mt = bx % 6;
            const int col0 = y * 128;
            const int bt_base = col0 / 197;
            const int col197  = (bt_base + 1) * 197;
            int bt1 = bt_base + 1; if (bt1 > 127) bt1 = 127;

            float bvsv[4][2][2];
            #pragma unroll
            for (int mi = 0; mi < 4; mi++)
                #pragma unroll
                for (int h = 0; h < 2; h++) {
                    int oc = g * 768 + mt * 128 + wm * 64 + mi * 16 + lr + h * 8;
                    float bv = bias[oc];
                    bvsv[mi][h][0] = bv * g_s[bt_base * 2304 + oc];
                    bvsv[mi][h][1] = bv * g_s[bt1 * 2304 + oc];
                }

            #pragma unroll
            for (int mi = 0; mi < 4; mi++)
                #pragma unroll
                for (int ni = 0; ni < 8; ni++)
                    #pragma unroll
                    for (int e = 0; e < 4; e++) {
                        const int h   = e >> 1;
                        const int oc  = g * 768 + mt * 128 + wm * 64 + mi * 16 + lr + h * 8;
                        const int col = col0 + wn * 64 + ni * 8 + lc * 2 + (e & 1);
                        const int bs  = (col >= col197) ? 1 : 0;
                        const float add = bs ? bvsv[mi][h][1] : bvsv[mi][h][0];
                        const size_t idx = (size_t)col + (size_t)oc * 197
                                         + (size_t)(bt_base + bs) * 453691;
                        out[idx] = acc[mi][ni][e] + add;
                    }
        }

        if (!has_next) break;
        t = tn; ap = apN; bp = bpN;
    }
}

extern "C" void kernel_launch(void* const* d_in, const int* in_sizes, int n_in,
                              void* d_out, int out_size)
{
    const float* x    = (const float*)d_in[0];
    const float* aw   = (const float*)d_in[1];
    const float* ab   = (const float*)d_in[2];
    const float* w    = (const float*)d_in[3];
    const float* bias = (const float*)d_in[4];
    float* out = (float*)d_out;

    cudaFuncSetAttribute(tal_main_kernel,
                         cudaFuncAttributeMaxDynamicSharedMemorySize, SMEM_MAIN);
    cudaFuncSetAttribute(routing_gemm,
                         cudaFuncAttributeMaxDynamicSharedMemorySize, SMEM_RT);

    prep_all<<<7040, 256>>>(aw, w, x);
    routing_gemm<<<dim3(18, 6), 128, SMEM_RT>>>();
    combine_s<<<BTOT * OC3 / 1024, 256>>>(ab);
    xs_fused<<<dim3(4, 3, BTOT), 96>>>(x);
    tal_main_kernel<<<NPERS, 128, SMEM_MAIN>>>(bias, out);
}